// round 2
// baseline (speedup 1.0000x reference)
#include <cuda_runtime.h>
#include <math.h>

// Problem constants
namespace {
constexpr int Bn = 4, Cn = 192, Tn = 2048, Hn = 2, Kd = 96;
constexpr int TQ = 64;         // queries per block
constexpr int BAND = 256;      // block-local mask half-width
constexpr int WIN = 4;         // relative-emb half-window
constexpr int SPAN = TQ + 2 * BAND;   // 576 keys per query tile
constexpr int NCH = SPAN / 64;        // 9 key chunks of 64
constexpr int SSTR = 592;      // S row stride (  %32==16 -> conflict-free writes)
constexpr int KVSTR = 97;      // q/k/v tile row stride ( %32==1 -> conflict-free)
constexpr int SMEM_FLOATS = TQ * SSTR          // S scores
                          + TQ * KVSTR         // q tile
                          + TQ * KVSTR         // k/v tile (shared)
                          + TQ * 12            // rq (rel-k per-query, 9 padded to 12)
                          + TQ                 // row sums
                          + 288;               // log1p table (257 used)
}

// Scratch (device globals: allocation-free rule)
__device__ __align__(16) float g_q[Bn * Tn * Cn];
__device__ __align__(16) float g_k[Bn * Tn * Cn];
__device__ __align__(16) float g_v[Bn * Tn * Cn];
__device__ __align__(16) float g_att[Bn * Tn * Cn];

// ---------------------------------------------------------------------------
// Q/K/V projections: out[b,t,d] = sum_c in[b,c,t] * W[c,d] + bias[d]
// grid (T/64, C/64, B*3), block (16,16)
// ---------------------------------------------------------------------------
__global__ void proj_kernel(const float* __restrict__ xin, const float* __restrict__ cin,
                            const float* __restrict__ Wq, const float* __restrict__ bq,
                            const float* __restrict__ Wk, const float* __restrict__ bk,
                            const float* __restrict__ Wv, const float* __restrict__ bv) {
    __shared__ float a_s[16][65];
    __shared__ float w_s[16][65];
    const int which = blockIdx.z % 3;
    const int b = blockIdx.z / 3;
    const float* in   = (which == 0) ? xin : cin;
    const float* W    = (which == 0) ? Wq : (which == 1) ? Wk : Wv;
    const float* bias = (which == 0) ? bq : (which == 1) ? bk : bv;
    float* out        = (which == 0) ? g_q : (which == 1) ? g_k : g_v;
    const int t0 = blockIdx.x * 64, d0 = blockIdx.y * 64;
    const int tx = threadIdx.x, ty = threadIdx.y, tid = ty * 16 + tx;
    const float* inb = in + b * Cn * Tn;
    float acc[4][4] = {};
    for (int k0 = 0; k0 < Cn; k0 += 16) {
#pragma unroll
        for (int r = 0; r < 4; r++) {
            int idx = tid + 256 * r;
            int kk = idx >> 6, cc = idx & 63;
            a_s[kk][cc] = inb[(k0 + kk) * Tn + t0 + cc];
            w_s[kk][cc] = W[(k0 + kk) * Cn + d0 + cc];
        }
        __syncthreads();
#pragma unroll
        for (int kk = 0; kk < 16; kk++) {
            float av[4], wv[4];
#pragma unroll
            for (int i = 0; i < 4; i++) av[i] = a_s[kk][ty + 16 * i];
#pragma unroll
            for (int j = 0; j < 4; j++) wv[j] = w_s[kk][tx + 16 * j];
#pragma unroll
            for (int i = 0; i < 4; i++)
#pragma unroll
                for (int j = 0; j < 4; j++) acc[i][j] += av[i] * wv[j];
        }
        __syncthreads();
    }
    float* ob = out + b * Tn * Cn;
#pragma unroll
    for (int i = 0; i < 4; i++) {
        int t = t0 + ty + 16 * i;
#pragma unroll
        for (int j = 0; j < 4; j++) {
            int d = d0 + tx + 16 * j;
            ob[t * Cn + d] = acc[i][j] + bias[d];
        }
    }
}

// ---------------------------------------------------------------------------
// Banded attention with relative position terms.
// grid (T/TQ, B*H), block (16,16), dynamic smem.
// ---------------------------------------------------------------------------
__global__ void attn_kernel(const float* __restrict__ embk, const float* __restrict__ embv,
                            const int* __restrict__ mask) {
    extern __shared__ float sm[];
    float* S    = sm;                      // [TQ][SSTR]
    float* qs   = S  + TQ * SSTR;          // [TQ][KVSTR]
    float* kv   = qs + TQ * KVSTR;         // [64][KVSTR]
    float* rq   = kv + TQ * KVSTR;         // [TQ][12]
    float* lr   = rq + TQ * 12;            // [TQ]
    float* prox = lr + TQ;                 // [257]

    const int tx = threadIdx.x, ty = threadIdx.y;
    const int tid = ty * 16 + tx;
    const int b = blockIdx.y / Hn, h = blockIdx.y % Hn;
    const int t0 = blockIdx.x * TQ;
    const int sbase = t0 - BAND;

    const float* Qb = g_q + (b * Tn) * Cn + h * Kd;
    const float* Kb = g_k + (b * Tn) * Cn + h * Kd;
    const float* Vb = g_v + (b * Tn) * Cn + h * Kd;

    // proximal bias table
    for (int i = tid; i <= BAND; i += 256) prox[i] = log1pf((float)i);

    // load Q tile (pre-scaled by 1/sqrt(K))
    const float qsc = 0.10206207261596575f;  // 96^-0.5
#pragma unroll
    for (int r = 0; r < 6; r++) {
        int idx = tid + 256 * r;
        int row = idx / 24, c4 = (idx % 24) * 4;
        float4 v = *reinterpret_cast<const float4*>(Qb + (t0 + row) * Cn + c4);
        float* d = qs + row * KVSTR + c4;
        d[0] = v.x * qsc; d[1] = v.y * qsc; d[2] = v.z * qsc; d[3] = v.w * qsc;
    }
    __syncthreads();

    // rel-K per-query logits: rq[q][m] = qs[q,:] . emb_rel_k[m,:]
    for (int idx = tid; idx < TQ * 9; idx += 256) {
        int q = idx / 9, m = idx - q * 9;
        const float* e  = embk + m * Kd;
        const float* qp = qs + q * KVSTR;
        float s = 0.f;
#pragma unroll 8
        for (int kk = 0; kk < Kd; kk++) s += qp[kk] * e[kk];
        rq[q * 12 + m] = s;
    }

    // ---- Phase A: scores (stream K in 9 chunks of 64) ----
    for (int ch = 0; ch < NCH; ch++) {
        __syncthreads();
#pragma unroll
        for (int r = 0; r < 6; r++) {
            int idx = tid + 256 * r;
            int row = idx / 24, c4 = (idx % 24) * 4;
            int s = sbase + ch * 64 + row;
            int sc = s < 0 ? 0 : (s >= Tn ? Tn - 1 : s);
            float4 v = *reinterpret_cast<const float4*>(Kb + sc * Cn + c4);
            float* d = kv + row * KVSTR + c4;
            d[0] = v.x; d[1] = v.y; d[2] = v.z; d[3] = v.w;
        }
        __syncthreads();
        float acc[4][4] = {};
#pragma unroll 4
        for (int kk = 0; kk < Kd; kk++) {
            float qv[4], kw[4];
#pragma unroll
            for (int i = 0; i < 4; i++) qv[i] = qs[(ty + 16 * i) * KVSTR + kk];
#pragma unroll
            for (int j = 0; j < 4; j++) kw[j] = kv[(tx + 16 * j) * KVSTR + kk];
#pragma unroll
            for (int i = 0; i < 4; i++)
#pragma unroll
                for (int j = 0; j < 4; j++) acc[i][j] += qv[i] * kw[j];
        }
#pragma unroll
        for (int i = 0; i < 4; i++) {
            int q = ty + 16 * i, t = t0 + q;
            const int* mp = mask + (b * Tn + t) * Tn;
#pragma unroll
            for (int j = 0; j < 4; j++) {
                int sl = tx + 16 * j;
                int s = sbase + ch * 64 + sl;
                int d = s - t;
                int ad = d < 0 ? -d : d;
                float v = acc[i][j];
                if (ad <= WIN) v += rq[q * 12 + d + WIN];
                v -= prox[ad <= BAND ? ad : BAND];
                bool valid = (s >= 0) && (s < Tn) && (ad <= BAND);
                if (valid) valid = (mp[s] != 0);
                S[q * SSTR + ch * 64 + sl] = valid ? v : -1e30f;
            }
        }
    }
    __syncthreads();

    // ---- Phase B: exact softmax stats (4 lanes per row) ----
    {
        int row = tid >> 2, lane = tid & 3;
        float* Sr = S + row * SSTR;
        float m = -1e30f;
        for (int c = lane; c < SPAN; c += 4) m = fmaxf(m, Sr[c]);
        m = fmaxf(m, __shfl_xor_sync(0xffffffffu, m, 1));
        m = fmaxf(m, __shfl_xor_sync(0xffffffffu, m, 2));
        float l = 0.f;
        for (int c = lane; c < SPAN; c += 4) {
            float e = expf(Sr[c] - m);   // masked (-1e30) -> exactly 0
            Sr[c] = e;
            l += e;
        }
        l += __shfl_xor_sync(0xffffffffu, l, 1);
        l += __shfl_xor_sync(0xffffffffu, l, 2);
        if (lane == 0) lr[row] = l;
    }

    // ---- Phase C: O = P @ V (stream V in 9 chunks) ----
    float o[4][6] = {};
    for (int ch = 0; ch < NCH; ch++) {
        __syncthreads();
#pragma unroll
        for (int r = 0; r < 6; r++) {
            int idx = tid + 256 * r;
            int row = idx / 24, c4 = (idx % 24) * 4;
            int s = sbase + ch * 64 + row;
            int sc = s < 0 ? 0 : (s >= Tn ? Tn - 1 : s);
            float4 v = *reinterpret_cast<const float4*>(Vb + sc * Cn + c4);
            float* d = kv + row * KVSTR + c4;
            d[0] = v.x; d[1] = v.y; d[2] = v.z; d[3] = v.w;
        }
        __syncthreads();
#pragma unroll 4
        for (int sl = 0; sl < 64; sl++) {
            float pv[4], vv[6];
#pragma unroll
            for (int i = 0; i < 4; i++) pv[i] = S[(ty + 16 * i) * SSTR + ch * 64 + sl];
#pragma unroll
            for (int j = 0; j < 6; j++) vv[j] = kv[sl * KVSTR + tx + 16 * j];
#pragma unroll
            for (int i = 0; i < 4; i++)
#pragma unroll
                for (int j = 0; j < 6; j++) o[i][j] += pv[i] * vv[j];
        }
    }

    // ---- Phase D: rel-V taps, normalize, store ----
#pragma unroll
    for (int i = 0; i < 4; i++) {
        int q = ty + 16 * i;
        float inv = 1.0f / lr[q];
#pragma unroll
        for (int m = 0; m < 9; m++) {
            // col of s = t + (m-4):  q + BAND - WIN + m
            float p = S[q * SSTR + q + (BAND - WIN) + m];
#pragma unroll
            for (int j = 0; j < 6; j++) o[i][j] += p * embv[m * Kd + tx + 16 * j];
        }
        float* ob = g_att + (b * Tn + t0 + q) * Cn + h * Kd;
#pragma unroll
        for (int j = 0; j < 6; j++) ob[tx + 16 * j] = o[i][j] * inv;
    }
}

// ---------------------------------------------------------------------------
// Output projection + transpose: y[b,co,t] = sum_d att[b,t,d]*Wo[d,co] + bo[co]
// grid (T/64, C/64, B), block (16,16)
// ---------------------------------------------------------------------------
__global__ void outproj_kernel(const float* __restrict__ Wo, const float* __restrict__ bo,
                               float* __restrict__ out) {
    __shared__ float a_s[16][65];   // [kk][t]
    __shared__ float w_s[16][65];   // [kk][co]
    const int b = blockIdx.z;
    const int t0 = blockIdx.x * 64, c0 = blockIdx.y * 64;
    const int tx = threadIdx.x, ty = threadIdx.y, tid = ty * 16 + tx;
    const float* ab = g_att + b * Tn * Cn;
    float acc[4][4] = {};
    for (int k0 = 0; k0 < Cn; k0 += 16) {
        {
            int ttRow = tid >> 2;          // 0..63
            int q4 = (tid & 3) * 4;        // 0,4,8,12
            float4 v = *reinterpret_cast<const float4*>(ab + (t0 + ttRow) * Cn + k0 + q4);
            a_s[q4 + 0][ttRow] = v.x; a_s[q4 + 1][ttRow] = v.y;
            a_s[q4 + 2][ttRow] = v.z; a_s[q4 + 3][ttRow] = v.w;
        }
#pragma unroll
        for (int r = 0; r < 4; r++) {
            int idx = tid + 256 * r;
            int kk = idx >> 6, cc = idx & 63;
            w_s[kk][cc] = Wo[(k0 + kk) * Cn + c0 + cc];
        }
        __syncthreads();
#pragma unroll
        for (int kk = 0; kk < 16; kk++) {
            float wv[4], av[4];
#pragma unroll
            for (int i = 0; i < 4; i++) wv[i] = w_s[kk][ty + 16 * i];
#pragma unroll
            for (int j = 0; j < 4; j++) av[j] = a_s[kk][tx + 16 * j];
#pragma unroll
            for (int i = 0; i < 4; i++)
#pragma unroll
                for (int j = 0; j < 4; j++) acc[i][j] += wv[i] * av[j];
        }
        __syncthreads();
    }
#pragma unroll
    for (int i = 0; i < 4; i++) {
        int co = c0 + ty + 16 * i;
        float bb = bo[co];
#pragma unroll
        for (int j = 0; j < 4; j++)
            out[(b * Cn + co) * Tn + t0 + tx + 16 * j] = acc[i][j] + bb;
    }
}

// ---------------------------------------------------------------------------
extern "C" void kernel_launch(void* const* d_in, const int* in_sizes, int n_in,
                              void* d_out, int out_size) {
    (void)in_sizes; (void)n_in; (void)out_size;
    const float* x   = (const float*)d_in[0];
    const float* c   = (const float*)d_in[1];
    const float* Wq  = (const float*)d_in[2];
    const float* bq  = (const float*)d_in[3];
    const float* Wk  = (const float*)d_in[4];
    const float* bk  = (const float*)d_in[5];
    const float* Wv  = (const float*)d_in[6];
    const float* bv  = (const float*)d_in[7];
    const float* Wo  = (const float*)d_in[8];
    const float* bo  = (const float*)d_in[9];
    const float* ek  = (const float*)d_in[10];
    const float* ev  = (const float*)d_in[11];
    const int*   msk = (const int*)d_in[12];

    const int smem_bytes = SMEM_FLOATS * (int)sizeof(float);
    cudaFuncSetAttribute(attn_kernel, cudaFuncAttributeMaxDynamicSharedMemorySize, smem_bytes);

    proj_kernel<<<dim3(Tn / 64, Cn / 64, Bn * 3), dim3(16, 16)>>>(x, c, Wq, bq, Wk, bk, Wv, bv);
    attn_kernel<<<dim3(Tn / TQ, Bn * Hn), dim3(16, 16), smem_bytes>>>(ek, ev, msk);
    outproj_kernel<<<dim3(Tn / 64, Cn / 64, Bn), dim3(16, 16)>>>(Wo, bo, (float*)d_out);
}

// round 4
// speedup vs baseline: 1.1727x; 1.1727x over previous
#include <cuda_runtime.h>
#include <math.h>

namespace {
constexpr int Bn = 4, Cn = 192, Tn = 2048, Hn = 2, Kd = 96;
constexpr int TQ = 64;
constexpr int BAND = 256;
constexpr int WIN = 4;
constexpr int SPAN = TQ + 2 * BAND;   // 576
constexpr int NCH = SPAN / 64;        // 9
constexpr int KVSTR = 97;             // odd stride -> conflict-free column reads
constexpr int PSTR = 80;              // 80*ty = 16ty mod32 -> conflict-free
constexpr int SMEM_FLOATS = 3 * TQ * KVSTR   // q, K, V tiles
                          + TQ * PSTR        // P chunk
                          + TQ * 12          // rq (rel-k taps)
                          + TQ * 12          // pTap (rel-v taps)
                          + TQ;              // row sums
constexpr int WSTR = 68;              // proj staging stride: 68*4B = 272B, 16B-aligned rows
}

__device__ __align__(16) float g_q[Bn * Tn * Cn];
__device__ __align__(16) float g_k[Bn * Tn * Cn];
__device__ __align__(16) float g_v[Bn * Tn * Cn];
__device__ __align__(16) float g_att[Bn * Tn * Cn];

// ---------------------------------------------------------------------------
// Q/K/V projections: out[b,t,d] = sum_c in[b,c,t] * W[c,d] + bias[d]
// ---------------------------------------------------------------------------
__global__ void proj_kernel(const float* __restrict__ xin, const float* __restrict__ cin,
                            const float* __restrict__ Wq, const float* __restrict__ bq,
                            const float* __restrict__ Wk, const float* __restrict__ bk,
                            const float* __restrict__ Wv, const float* __restrict__ bv) {
    __shared__ __align__(16) float a_s[16][WSTR];
    __shared__ __align__(16) float w_s[16][WSTR];
    const int which = blockIdx.z % 3;
    const int b = blockIdx.z / 3;
    const float* in   = (which == 0) ? xin : cin;
    const float* W    = (which == 0) ? Wq : (which == 1) ? Wk : Wv;
    const float* bias = (which == 0) ? bq : (which == 1) ? bk : bv;
    float* out        = (which == 0) ? g_q : (which == 1) ? g_k : g_v;
    const int t0 = blockIdx.x * 64, d0 = blockIdx.y * 64;
    const int tx = threadIdx.x, ty = threadIdx.y, tid = ty * 16 + tx;
    const int lkk = tid >> 4, lc4 = (tid & 15) * 4;
    const float* inb = in + b * Cn * Tn;
    float acc[4][4] = {};
    for (int k0 = 0; k0 < Cn; k0 += 16) {
        {
            float4 av = *reinterpret_cast<const float4*>(inb + (k0 + lkk) * Tn + t0 + lc4);
            float4 wv = *reinterpret_cast<const float4*>(W + (k0 + lkk) * Cn + d0 + lc4);
            *reinterpret_cast<float4*>(&a_s[lkk][lc4]) = av;
            *reinterpret_cast<float4*>(&w_s[lkk][lc4]) = wv;
        }
        __syncthreads();
#pragma unroll
        for (int kk = 0; kk < 16; kk++) {
            float av[4], wv[4];
#pragma unroll
            for (int i = 0; i < 4; i++) av[i] = a_s[kk][ty + 16 * i];
#pragma unroll
            for (int j = 0; j < 4; j++) wv[j] = w_s[kk][tx + 16 * j];
#pragma unroll
            for (int i = 0; i < 4; i++)
#pragma unroll
                for (int j = 0; j < 4; j++) acc[i][j] += av[i] * wv[j];
        }
        __syncthreads();
    }
    float* ob = out + b * Tn * Cn;
#pragma unroll
    for (int i = 0; i < 4; i++) {
        int t = t0 + ty + 16 * i;
#pragma unroll
        for (int j = 0; j < 4; j++) {
            int d = d0 + tx + 16 * j;
            ob[t * Cn + d] = acc[i][j] + bias[d];
        }
    }
}

// ---------------------------------------------------------------------------
// Single-pass banded attention (no max subtraction: scores are O(1)).
// grid (T/64, B*H), block (16,16), 101KB dyn smem -> 2 CTAs/SM, one wave.
// ---------------------------------------------------------------------------
__global__ void __launch_bounds__(256)
attn_kernel(const float* __restrict__ embk, const float* __restrict__ embv,
            const int* __restrict__ mask) {
    extern __shared__ float sm[];
    float* qs   = sm;                   // [64][97]
    float* Ks   = qs + TQ * KVSTR;      // [64][97]
    float* Vs   = Ks + TQ * KVSTR;      // [64][97]
    float* P    = Vs + TQ * KVSTR;      // [64][80]
    float* rq   = P + TQ * PSTR;        // [64][12]
    float* pTap = rq + TQ * 12;         // [64][12]
    float* lr   = pTap + TQ * 12;       // [64]

    const int tx = threadIdx.x, ty = threadIdx.y;
    const int tid = ty * 16 + tx;
    const int b = blockIdx.y / Hn, h = blockIdx.y % Hn;
    const int t0 = blockIdx.x * TQ;
    const int sbase = t0 - BAND;

    const float* Qb = g_q + (b * Tn) * Cn + h * Kd;
    const float* Kb = g_k + (b * Tn) * Cn + h * Kd;
    const float* Vb = g_v + (b * Tn) * Cn + h * Kd;

    // zero rel-v taps
    for (int i = tid; i < TQ * 12; i += 256) pTap[i] = 0.f;

    // load Q (pre-scaled by K^-0.5)
    const float qsc = 0.10206207261596575f;
#pragma unroll
    for (int r = 0; r < 6; r++) {
        int idx = tid + 256 * r;
        int row = idx / 24, c4 = (idx % 24) * 4;
        float4 v = *reinterpret_cast<const float4*>(Qb + (t0 + row) * Cn + c4);
        float* d = qs + row * KVSTR + c4;
        d[0] = v.x * qsc; d[1] = v.y * qsc; d[2] = v.z * qsc; d[3] = v.w * qsc;
    }
    __syncthreads();

    // rel-K per-query logits
    for (int idx = tid; idx < TQ * 9; idx += 256) {
        int q = idx / 9, m = idx - q * 9;
        const float* e  = embk + m * Kd;
        const float* qp = qs + q * KVSTR;
        float s = 0.f;
#pragma unroll 8
        for (int kk = 0; kk < Kd; kk++) s += qp[kk] * e[kk];
        rq[q * 12 + m] = s;
    }

    float o[4][6] = {};
    float lsum[4] = {};

    for (int ch = 0; ch < NCH; ch++) {
        __syncthreads();   // prev PV done -> Vs/P reusable
        // load K and V chunks
#pragma unroll
        for (int r = 0; r < 6; r++) {
            int idx = tid + 256 * r;
            int row = idx / 24, c4 = (idx % 24) * 4;
            int s = sbase + ch * 64 + row;
            int sc = s < 0 ? 0 : (s >= Tn ? Tn - 1 : s);
            float4 kvv = *reinterpret_cast<const float4*>(Kb + sc * Cn + c4);
            float4 vvv = *reinterpret_cast<const float4*>(Vb + sc * Cn + c4);
            float* dk = Ks + row * KVSTR + c4;
            float* dv = Vs + row * KVSTR + c4;
            dk[0] = kvv.x; dk[1] = kvv.y; dk[2] = kvv.z; dk[3] = kvv.w;
            dv[0] = vvv.x; dv[1] = vvv.y; dv[2] = vvv.z; dv[3] = vvv.w;
        }
        __syncthreads();

        // QK^T 4x4 microtile
        float acc[4][4] = {};
#pragma unroll 4
        for (int kk = 0; kk < Kd; kk++) {
            float qv[4], kw[4];
#pragma unroll
            for (int i = 0; i < 4; i++) qv[i] = qs[(ty + 16 * i) * KVSTR + kk];
#pragma unroll
            for (int j = 0; j < 4; j++) kw[j] = Ks[(tx + 16 * j) * KVSTR + kk];
#pragma unroll
            for (int i = 0; i < 4; i++)
#pragma unroll
                for (int j = 0; j < 4; j++) acc[i][j] += qv[i] * kw[j];
        }

        // epilogue: bias + mask + exp, P & taps & partial row-sums
#pragma unroll
        for (int i = 0; i < 4; i++) {
            int q = ty + 16 * i, t = t0 + q;
            const int* mp = mask + (b * Tn + t) * Tn;
#pragma unroll
            for (int j = 0; j < 4; j++) {
                int sl = tx + 16 * j;
                int s = sbase + ch * 64 + sl;
                int d = s - t;
                int ad = d < 0 ? -d : d;
                float v = acc[i][j];
                if (ad <= WIN) v += rq[q * 12 + d + WIN];
                v -= __logf(1.0f + (float)ad);
                bool valid = (s >= 0) && (s < Tn) && (ad <= BAND);
                if (valid) valid = (mp[s] != 0);
                float e = valid ? __expf(v) : 0.f;
                P[q * PSTR + sl] = e;
                if (ad <= WIN) pTap[q * 12 + d + WIN] = e;
                lsum[i] += e;
            }
        }
        __syncthreads();   // P complete

        // O += P @ V
#pragma unroll 4
        for (int sl = 0; sl < 64; sl++) {
            float pv[4], vv[6];
#pragma unroll
            for (int i = 0; i < 4; i++) pv[i] = P[(ty + 16 * i) * PSTR + sl];
#pragma unroll
            for (int j = 0; j < 6; j++) vv[j] = Vs[sl * KVSTR + tx + 16 * j];
#pragma unroll
            for (int i = 0; i < 4; i++)
#pragma unroll
                for (int j = 0; j < 6; j++) o[i][j] += pv[i] * vv[j];
        }
    }

    // reduce row sums across the 16 tx lanes (half-warp)
#pragma unroll
    for (int i = 0; i < 4; i++) {
        float l = lsum[i];
        l += __shfl_xor_sync(0xffffffffu, l, 1);
        l += __shfl_xor_sync(0xffffffffu, l, 2);
        l += __shfl_xor_sync(0xffffffffu, l, 4);
        l += __shfl_xor_sync(0xffffffffu, l, 8);
        if (tx == 0) lr[ty + 16 * i] = l;
    }
    __syncthreads();

    // rel-V taps + normalize + store
#pragma unroll
    for (int i = 0; i < 4; i++) {
        int q = ty + 16 * i;
        float inv = 1.0f / lr[q];
#pragma unroll
        for (int m = 0; m < 9; m++) {
            float p = pTap[q * 12 + m];
#pragma unroll
            for (int j = 0; j < 6; j++) o[i][j] += p * embv[m * Kd + tx + 16 * j];
        }
        float* ob = g_att + (b * Tn + t0 + q) * Cn + h * Kd;
#pragma unroll
        for (int j = 0; j < 6; j++) ob[tx + 16 * j] = o[i][j] * inv;
    }
}

// ---------------------------------------------------------------------------
// Output projection + transpose
// ---------------------------------------------------------------------------
__global__ void outproj_kernel(const float* __restrict__ Wo, const float* __restrict__ bo,
                               float* __restrict__ out) {
    __shared__ __align__(16) float a_s[16][WSTR];
    __shared__ __align__(16) float w_s[16][WSTR];
    const int b = blockIdx.z;
    const int t0 = blockIdx.x * 64, c0 = blockIdx.y * 64;
    const int tx = threadIdx.x, ty = threadIdx.y, tid = ty * 16 + tx;
    const int lkk = tid >> 4, lc4 = (tid & 15) * 4;
    const float* ab = g_att + b * Tn * Cn;
    float acc[4][4] = {};
    for (int k0 = 0; k0 < Cn; k0 += 16) {
        {
            int ttRow = tid >> 2;
            int q4 = (tid & 3) * 4;
            float4 v = *reinterpret_cast<const float4*>(ab + (t0 + ttRow) * Cn + k0 + q4);
            a_s[q4 + 0][ttRow] = v.x; a_s[q4 + 1][ttRow] = v.y;
            a_s[q4 + 2][ttRow] = v.z; a_s[q4 + 3][ttRow] = v.w;
            float4 wv = *reinterpret_cast<const float4*>(Wo + (k0 + lkk) * Cn + c0 + lc4);
            *reinterpret_cast<float4*>(&w_s[lkk][lc4]) = wv;
        }
        __syncthreads();
#pragma unroll
        for (int kk = 0; kk < 16; kk++) {
            float wv[4], av[4];
#pragma unroll
            for (int i = 0; i < 4; i++) wv[i] = w_s[kk][ty + 16 * i];
#pragma unroll
            for (int j = 0; j < 4; j++) av[j] = a_s[kk][tx + 16 * j];
#pragma unroll
            for (int i = 0; i < 4; i++)
#pragma unroll
                for (int j = 0; j < 4; j++) acc[i][j] += wv[i] * av[j];
        }
        __syncthreads();
    }
#pragma unroll
    for (int i = 0; i < 4; i++) {
        int co = c0 + ty + 16 * i;
        float bb = bo[co];
#pragma unroll
        for (int j = 0; j < 4; j++)
            out[(b * Cn + co) * Tn + t0 + tx + 16 * j] = acc[i][j] + bb;
    }
}

// ---------------------------------------------------------------------------
extern "C" void kernel_launch(void* const* d_in, const int* in_sizes, int n_in,
                              void* d_out, int out_size) {
    (void)in_sizes; (void)n_in; (void)out_size;
    const float* x   = (const float*)d_in[0];
    const float* c   = (const float*)d_in[1];
    const float* Wq  = (const float*)d_in[2];
    const float* bq  = (const float*)d_in[3];
    const float* Wk  = (const float*)d_in[4];
    const float* bk  = (const float*)d_in[5];
    const float* Wv  = (const float*)d_in[6];
    const float* bv  = (const float*)d_in[7];
    const float* Wo  = (const float*)d_in[8];
    const float* bo  = (const float*)d_in[9];
    const float* ek  = (const float*)d_in[10];
    const float* ev  = (const float*)d_in[11];
    const int*   msk = (const int*)d_in[12];

    const int smem_bytes = SMEM_FLOATS * (int)sizeof(float);
    cudaFuncSetAttribute(attn_kernel, cudaFuncAttributeMaxDynamicSharedMemorySize, smem_bytes);

    proj_kernel<<<dim3(Tn / 64, Cn / 64, Bn * 3), dim3(16, 16)>>>(x, c, Wq, bq, Wk, bk, Wv, bv);
    attn_kernel<<<dim3(Tn / TQ, Bn * Hn), dim3(16, 16), smem_bytes>>>(ek, ev, msk);
    outproj_kernel<<<dim3(Tn / 64, Cn / 64, Bn), dim3(16, 16)>>>(Wo, bo, (float*)d_out);
}

// round 5
// speedup vs baseline: 1.2463x; 1.0627x over previous
#include <cuda_runtime.h>
#include <math.h>

namespace {
constexpr int Bn = 4, Cn = 192, Tn = 2048, Hn = 2, Kd = 96;
constexpr int TQ = 64;
constexpr int BAND = 256;
constexpr int WIN = 4;
constexpr int SPAN = TQ + 2 * BAND;   // 576
constexpr int NCH = SPAN / 64;        // 9
constexpr int QKSTR = 98;             // even (LDS.64 over kk), %32==2
constexpr int VTSTR = 66;             // Vt[d][sl] stride, even, %32==2
constexpr int PSTR  = 80;             // even
constexpr int SMEM_FLOATS = 2 * TQ * QKSTR     // qs, Ks
                          + Kd * VTSTR         // Vt
                          + TQ * PSTR          // P
                          + TQ * 12            // rq
                          + TQ * 12            // pTap
                          + TQ                 // lr
                          + 260;               // prox table
constexpr int TSTR = 18;              // transposed staging stride (even)
}

__device__ __align__(16) float g_q[Bn * Tn * Cn];
__device__ __align__(16) float g_k[Bn * Tn * Cn];
__device__ __align__(16) float g_v[Bn * Tn * Cn];
__device__ __align__(16) float g_att[Bn * Tn * Cn];

typedef unsigned long long u64t;

__device__ __forceinline__ u64t fma2(u64t a, u64t b, u64t c) {
    u64t d;
    asm("fma.rn.f32x2 %0, %1, %2, %3;" : "=l"(d) : "l"(a), "l"(b), "l"(c));
    return d;
}
__device__ __forceinline__ float lohi_sum(u64t v) {
    float2 f = *reinterpret_cast<float2*>(&v);
    return f.x + f.y;
}
__device__ __forceinline__ u64t lds2(const float* p) {
    return *reinterpret_cast<const u64t*>(p);
}

// ---------------------------------------------------------------------------
// Q/K/V projections: out[b,t,d] = sum_c in[b,c,t] * W[c,d] + bias[d]
// Staging transposed to [x][kk] (stride 18) so the kk reduction pairs into
// f32x2 lanes with contiguous LDS.64 operands.
// ---------------------------------------------------------------------------
__global__ void proj_kernel(const float* __restrict__ xin, const float* __restrict__ cin,
                            const float* __restrict__ Wq, const float* __restrict__ bq,
                            const float* __restrict__ Wk, const float* __restrict__ bk,
                            const float* __restrict__ Wv, const float* __restrict__ bv) {
    __shared__ __align__(16) float a_s[64][TSTR];   // [t][kk]
    __shared__ __align__(16) float w_s[64][TSTR];   // [d][kk]
    const int which = blockIdx.z % 3;
    const int b = blockIdx.z / 3;
    const float* in   = (which == 0) ? xin : cin;
    const float* W    = (which == 0) ? Wq : (which == 1) ? Wk : Wv;
    const float* bias = (which == 0) ? bq : (which == 1) ? bk : bv;
    float* out        = (which == 0) ? g_q : (which == 1) ? g_k : g_v;
    const int t0 = blockIdx.x * 64, d0 = blockIdx.y * 64;
    const int tx = threadIdx.x, ty = threadIdx.y, tid = ty * 16 + tx;
    const int lkk = tid >> 4, lc4 = (tid & 15) * 4;
    const float* inb = in + b * Cn * Tn;
    u64t acc2[4][4] = {};
    for (int k0 = 0; k0 < Cn; k0 += 16) {
        {
            float4 av = *reinterpret_cast<const float4*>(inb + (k0 + lkk) * Tn + t0 + lc4);
            float4 wv = *reinterpret_cast<const float4*>(W + (k0 + lkk) * Cn + d0 + lc4);
            a_s[lc4 + 0][lkk] = av.x; a_s[lc4 + 1][lkk] = av.y;
            a_s[lc4 + 2][lkk] = av.z; a_s[lc4 + 3][lkk] = av.w;
            w_s[lc4 + 0][lkk] = wv.x; w_s[lc4 + 1][lkk] = wv.y;
            w_s[lc4 + 2][lkk] = wv.z; w_s[lc4 + 3][lkk] = wv.w;
        }
        __syncthreads();
#pragma unroll
        for (int kk = 0; kk < 16; kk += 2) {
            u64t a2[4], w2[4];
#pragma unroll
            for (int i = 0; i < 4; i++) a2[i] = lds2(&a_s[ty + 16 * i][kk]);
#pragma unroll
            for (int j = 0; j < 4; j++) w2[j] = lds2(&w_s[tx + 16 * j][kk]);
#pragma unroll
            for (int i = 0; i < 4; i++)
#pragma unroll
                for (int j = 0; j < 4; j++) acc2[i][j] = fma2(a2[i], w2[j], acc2[i][j]);
        }
        __syncthreads();
    }
    float* ob = out + b * Tn * Cn;
#pragma unroll
    for (int i = 0; i < 4; i++) {
        int t = t0 + ty + 16 * i;
#pragma unroll
        for (int j = 0; j < 4; j++) {
            int d = d0 + tx + 16 * j;
            ob[t * Cn + d] = lohi_sum(acc2[i][j]) + bias[d];
        }
    }
}

// ---------------------------------------------------------------------------
// Single-pass banded attention, f32x2 packed FMA in both GEMM loops.
// grid (T/64, B*H), block (16,16), ~102KB dyn smem -> 2 CTAs/SM (forced).
// ---------------------------------------------------------------------------
__global__ void __launch_bounds__(256, 2)
attn_kernel(const float* __restrict__ embk, const float* __restrict__ embv,
            const int* __restrict__ mask) {
    extern __shared__ float sm[];
    float* qs   = sm;                     // [64][98]
    float* Ks   = qs + TQ * QKSTR;        // [64][98]
    float* Vt   = Ks + TQ * QKSTR;        // [96][66]  (d-major, sl contiguous)
    float* P    = Vt + Kd * VTSTR;        // [64][80]
    float* rq   = P + TQ * PSTR;          // [64][12]
    float* pTap = rq + TQ * 12;           // [64][12]
    float* lr   = pTap + TQ * 12;         // [64]
    float* prox = lr + TQ;                // [260]

    const int tx = threadIdx.x, ty = threadIdx.y;
    const int tid = ty * 16 + tx;
    const int b = blockIdx.y / Hn, h = blockIdx.y % Hn;
    const int t0 = blockIdx.x * TQ;
    const int sbase = t0 - BAND;

    const float* Qb = g_q + (b * Tn) * Cn + h * Kd;
    const float* Kb = g_k + (b * Tn) * Cn + h * Kd;
    const float* Vb = g_v + (b * Tn) * Cn + h * Kd;

    for (int i = tid; i < TQ * 12; i += 256) pTap[i] = 0.f;
    for (int i = tid; i <= BAND; i += 256) prox[i] = log1pf((float)i);

    const float qsc = 0.10206207261596575f;
#pragma unroll
    for (int r = 0; r < 6; r++) {
        int idx = tid + 256 * r;
        int row = idx / 24, c4 = (idx % 24) * 4;
        float4 v = *reinterpret_cast<const float4*>(Qb + (t0 + row) * Cn + c4);
        float* d = qs + row * QKSTR + c4;
        d[0] = v.x * qsc; d[1] = v.y * qsc; d[2] = v.z * qsc; d[3] = v.w * qsc;
    }
    __syncthreads();

    // rel-K per-query logits
    for (int idx = tid; idx < TQ * 9; idx += 256) {
        int q = idx / 9, m = idx - q * 9;
        const float* e  = embk + m * Kd;
        const float* qp = qs + q * QKSTR;
        float s = 0.f;
#pragma unroll 8
        for (int kk = 0; kk < Kd; kk++) s += qp[kk] * e[kk];
        rq[q * 12 + m] = s;
    }

    float o[4][6] = {};
    float lsum[4] = {};

    for (int ch = 0; ch < NCH; ch++) {
        __syncthreads();
        // load K chunk (row-major) + V chunk transposed into Vt[d][sl]
#pragma unroll
        for (int r = 0; r < 6; r++) {
            int idx = tid + 256 * r;
            int row = idx / 24, c4 = (idx % 24) * 4;
            int s = sbase + ch * 64 + row;
            int sc = s < 0 ? 0 : (s >= Tn ? Tn - 1 : s);
            float4 kvv = *reinterpret_cast<const float4*>(Kb + sc * Cn + c4);
            float4 vvv = *reinterpret_cast<const float4*>(Vb + sc * Cn + c4);
            float* dk = Ks + row * QKSTR + c4;
            dk[0] = kvv.x; dk[1] = kvv.y; dk[2] = kvv.z; dk[3] = kvv.w;
            Vt[(c4 + 0) * VTSTR + row] = vvv.x;
            Vt[(c4 + 1) * VTSTR + row] = vvv.y;
            Vt[(c4 + 2) * VTSTR + row] = vvv.z;
            Vt[(c4 + 3) * VTSTR + row] = vvv.w;
        }
        __syncthreads();

        // QK^T 4x4 microtile, kk paired into f32x2
        u64t acc2[4][4] = {};
#pragma unroll 4
        for (int kk = 0; kk < Kd; kk += 2) {
            u64t q2[4], k2[4];
#pragma unroll
            for (int i = 0; i < 4; i++) q2[i] = lds2(&qs[(ty + 16 * i) * QKSTR + kk]);
#pragma unroll
            for (int j = 0; j < 4; j++) k2[j] = lds2(&Ks[(tx + 16 * j) * QKSTR + kk]);
#pragma unroll
            for (int i = 0; i < 4; i++)
#pragma unroll
                for (int j = 0; j < 4; j++) acc2[i][j] = fma2(q2[i], k2[j], acc2[i][j]);
        }

        // epilogue: bias + mask + exp
#pragma unroll
        for (int i = 0; i < 4; i++) {
            int q = ty + 16 * i, t = t0 + q;
            const int* mp = mask + (b * Tn + t) * Tn;
#pragma unroll
            for (int j = 0; j < 4; j++) {
                int sl = tx + 16 * j;
                int s = sbase + ch * 64 + sl;
                int d = s - t;
                int ad = d < 0 ? -d : d;
                float v = lohi_sum(acc2[i][j]);
                if (ad <= WIN) v += rq[q * 12 + d + WIN];
                v -= prox[ad <= BAND ? ad : BAND];
                bool valid = (s >= 0) && (s < Tn) && (ad <= BAND);
                if (valid) valid = (mp[s] != 0);
                float e = valid ? __expf(v) : 0.f;
                P[q * PSTR + sl] = e;
                if (ad <= WIN) pTap[q * 12 + d + WIN] = e;
                lsum[i] += e;
            }
        }
        __syncthreads();

        // O += P @ V, sl paired into f32x2 (Vt transposed -> contiguous sl)
        u64t o2[4][6] = {};
#pragma unroll 4
        for (int sl = 0; sl < 64; sl += 2) {
            u64t p2[4], v2[6];
#pragma unroll
            for (int i = 0; i < 4; i++) p2[i] = lds2(&P[(ty + 16 * i) * PSTR + sl]);
#pragma unroll
            for (int j = 0; j < 6; j++) v2[j] = lds2(&Vt[(tx + 16 * j) * VTSTR + sl]);
#pragma unroll
            for (int i = 0; i < 4; i++)
#pragma unroll
                for (int j = 0; j < 6; j++) o2[i][j] = fma2(p2[i], v2[j], o2[i][j]);
        }
#pragma unroll
        for (int i = 0; i < 4; i++)
#pragma unroll
            for (int j = 0; j < 6; j++) o[i][j] += lohi_sum(o2[i][j]);
    }

    // reduce row sums across the 16 tx lanes
#pragma unroll
    for (int i = 0; i < 4; i++) {
        float l = lsum[i];
        l += __shfl_xor_sync(0xffffffffu, l, 1);
        l += __shfl_xor_sync(0xffffffffu, l, 2);
        l += __shfl_xor_sync(0xffffffffu, l, 4);
        l += __shfl_xor_sync(0xffffffffu, l, 8);
        if (tx == 0) lr[ty + 16 * i] = l;
    }
    __syncthreads();

    // rel-V taps + normalize + store
#pragma unroll
    for (int i = 0; i < 4; i++) {
        int q = ty + 16 * i;
        float inv = 1.0f / lr[q];
#pragma unroll
        for (int m = 0; m < 9; m++) {
            float p = pTap[q * 12 + m];
#pragma unroll
            for (int j = 0; j < 6; j++) o[i][j] += p * embv[m * Kd + tx + 16 * j];
        }
        float* ob = g_att + (b * Tn + t0 + q) * Cn + h * Kd;
#pragma unroll
        for (int j = 0; j < 6; j++) ob[tx + 16 * j] = o[i][j] * inv;
    }
}

// ---------------------------------------------------------------------------
// Output projection + transpose: y[b,co,t] = sum_d att[b,t,d]*Wo[d,co]+bo[co]
// ---------------------------------------------------------------------------
__global__ void outproj_kernel(const float* __restrict__ Wo, const float* __restrict__ bo,
                               float* __restrict__ out) {
    __shared__ __align__(16) float a_s[64][TSTR];   // [t][dd]
    __shared__ __align__(16) float w_s[64][TSTR];   // [co][dd]
    const int b = blockIdx.z;
    const int t0 = blockIdx.x * 64, c0 = blockIdx.y * 64;
    const int tx = threadIdx.x, ty = threadIdx.y, tid = ty * 16 + tx;
    const int lkk = tid >> 4, lc4 = (tid & 15) * 4;
    const float* ab = g_att + b * Tn * Cn;
    u64t acc2[4][4] = {};
    for (int k0 = 0; k0 < Cn; k0 += 16) {
        {
            int ttRow = tid >> 2;
            int q4 = (tid & 3) * 4;
            float4 v = *reinterpret_cast<const float4*>(ab + (t0 + ttRow) * Cn + k0 + q4);
            a_s[ttRow][q4 + 0] = v.x; a_s[ttRow][q4 + 1] = v.y;
            a_s[ttRow][q4 + 2] = v.z; a_s[ttRow][q4 + 3] = v.w;
            float4 wv = *reinterpret_cast<const float4*>(Wo + (k0 + lkk) * Cn + c0 + lc4);
            w_s[lc4 + 0][lkk] = wv.x; w_s[lc4 + 1][lkk] = wv.y;
            w_s[lc4 + 2][lkk] = wv.z; w_s[lc4 + 3][lkk] = wv.w;
        }
        __syncthreads();
#pragma unroll
        for (int kk = 0; kk < 16; kk += 2) {
            u64t w2[4], a2[4];
#pragma unroll
            for (int i = 0; i < 4; i++) w2[i] = lds2(&w_s[ty + 16 * i][kk]);
#pragma unroll
            for (int j = 0; j < 4; j++) a2[j] = lds2(&a_s[tx + 16 * j][kk]);
#pragma unroll
            for (int i = 0; i < 4; i++)
#pragma unroll
                for (int j = 0; j < 4; j++) acc2[i][j] = fma2(w2[i], a2[j], acc2[i][j]);
        }
        __syncthreads();
    }
#pragma unroll
    for (int i = 0; i < 4; i++) {
        int co = c0 + ty + 16 * i;
        float bb = bo[co];
#pragma unroll
        for (int j = 0; j < 4; j++)
            out[(b * Cn + co) * Tn + t0 + tx + 16 * j] = lohi_sum(acc2[i][j]) + bb;
    }
}

// ---------------------------------------------------------------------------
extern "C" void kernel_launch(void* const* d_in, const int* in_sizes, int n_in,
                              void* d_out, int out_size) {
    (void)in_sizes; (void)n_in; (void)out_size;
    const float* x   = (const float*)d_in[0];
    const float* c   = (const float*)d_in[1];
    const float* Wq  = (const float*)d_in[2];
    const float* bq  = (const float*)d_in[3];
    const float* Wk  = (const float*)d_in[4];
    const float* bk  = (const float*)d_in[5];
    const float* Wv  = (const float*)d_in[6];
    const float* bv  = (const float*)d_in[7];
    const float* Wo  = (const float*)d_in[8];
    const float* bo  = (const float*)d_in[9];
    const float* ek  = (const float*)d_in[10];
    const float* ev  = (const float*)d_in[11];
    const int*   msk = (const int*)d_in[12];

    const int smem_bytes = SMEM_FLOATS * (int)sizeof(float);
    cudaFuncSetAttribute(attn_kernel, cudaFuncAttributeMaxDynamicSharedMemorySize, smem_bytes);

    proj_kernel<<<dim3(Tn / 64, Cn / 64, Bn * 3), dim3(16, 16)>>>(x, c, Wq, bq, Wk, bk, Wv, bv);
    attn_kernel<<<dim3(Tn / TQ, Bn * Hn), dim3(16, 16), smem_bytes>>>(ek, ev, msk);
    outproj_kernel<<<dim3(Tn / 64, Cn / 64, Bn), dim3(16, 16)>>>(Wo, bo, (float*)d_out);
}

// round 6
// speedup vs baseline: 1.3824x; 1.1092x over previous
#include <cuda_runtime.h>
#include <math.h>

namespace {
constexpr int Bn = 4, Cn = 192, Tn = 2048, Hn = 2, Kd = 96;
constexpr int TQ = 64;
constexpr int BAND = 256;
constexpr int WIN = 4;
constexpr int SPAN = TQ + 2 * BAND;   // 576
constexpr int NCH = SPAN / 64;        // 9
constexpr int KVS  = 100;             // q/K/V stride: mult of 4 (cp.async 16B rows), even (LDS.64)
constexpr int PSTR = 80;              // P stride (even, conflict-free)
constexpr int GSTR = 196;             // gemm staging stride: mult of 4, even
constexpr int ATTN_SMEM_FLOATS = 3 * TQ * KVS + TQ * PSTR + TQ * 12 + TQ * 12 + TQ + 260;
constexpr int GEMM_SMEM_BYTES  = 2 * 64 * GSTR * 4;   // ~98KB
}

__device__ __align__(16) float g_q[Bn * Tn * Cn];
__device__ __align__(16) float g_k[Bn * Tn * Cn];
__device__ __align__(16) float g_v[Bn * Tn * Cn];
__device__ __align__(16) float g_att[Bn * Tn * Cn];

typedef unsigned long long u64t;

__device__ __forceinline__ u64t fma2(u64t a, u64t b, u64t c) {
    u64t d;
    asm("fma.rn.f32x2 %0, %1, %2, %3;" : "=l"(d) : "l"(a), "l"(b), "l"(c));
    return d;
}
__device__ __forceinline__ float lohi_sum(u64t v) {
    float2 f = *reinterpret_cast<float2*>(&v);
    return f.x + f.y;
}
__device__ __forceinline__ float2 unpk(u64t v) { return *reinterpret_cast<float2*>(&v); }
__device__ __forceinline__ u64t lds2(const float* p) {
    return *reinterpret_cast<const u64t*>(p);
}
__device__ __forceinline__ u64t dup2(float p) {
    u64t r;
    asm("mov.b64 %0, {%1, %1};" : "=l"(r) : "f"(p));
    return r;
}
__device__ __forceinline__ void cpa16(float* s, const float* g) {
    asm volatile("cp.async.cg.shared.global [%0], [%1], 16;"
                 :: "r"((unsigned)__cvta_generic_to_shared(s)), "l"(g));
}
__device__ __forceinline__ void cpa_commit() { asm volatile("cp.async.commit_group;"); }
__device__ __forceinline__ void cpa_wait0()  { asm volatile("cp.async.wait_group 0;"); }

// ---------------------------------------------------------------------------
// Q/K/V projections, single-fill: stage full 64x192 A and W tiles (transposed
// to kk-contiguous), one sync, then sync-free FFMA2 loop.
// ---------------------------------------------------------------------------
__global__ void __launch_bounds__(256)
proj_kernel(const float* __restrict__ xin, const float* __restrict__ cin,
            const float* __restrict__ Wq, const float* __restrict__ bq,
            const float* __restrict__ Wk, const float* __restrict__ bk,
            const float* __restrict__ Wv, const float* __restrict__ bv) {
    extern __shared__ float smp[];
    float* a_s = smp;               // [64][196]  (t, kk)
    float* w_s = smp + 64 * GSTR;   // [64][196]  (d, kk)
    const int which = blockIdx.z % 3;
    const int b = blockIdx.z / 3;
    const float* in   = (which == 0) ? xin : cin;
    const float* W    = (which == 0) ? Wq : (which == 1) ? Wk : Wv;
    const float* bias = (which == 0) ? bq : (which == 1) ? bk : bv;
    float* out        = (which == 0) ? g_q : (which == 1) ? g_k : g_v;
    const int t0 = blockIdx.x * 64, d0 = blockIdx.y * 64;
    const int tx = threadIdx.x, ty = threadIdx.y, tid = ty * 16 + tx;
    const float* inb = in + b * Cn * Tn;

    // fill A (transpose [kk][t] -> [t][kk])
    {
        float4 va[12];
#pragma unroll
        for (int r = 0; r < 12; r++) {
            int idx = tid + 256 * r;
            int kk = idx >> 4, q4 = (idx & 15) * 4;
            va[r] = *reinterpret_cast<const float4*>(inb + kk * Tn + t0 + q4);
        }
#pragma unroll
        for (int r = 0; r < 12; r++) {
            int idx = tid + 256 * r;
            int kk = idx >> 4, q4 = (idx & 15) * 4;
            a_s[(q4 + 0) * GSTR + kk] = va[r].x;
            a_s[(q4 + 1) * GSTR + kk] = va[r].y;
            a_s[(q4 + 2) * GSTR + kk] = va[r].z;
            a_s[(q4 + 3) * GSTR + kk] = va[r].w;
        }
    }
    // fill W (transpose [kk][d] -> [d][kk])
    {
        float4 vw[12];
#pragma unroll
        for (int r = 0; r < 12; r++) {
            int idx = tid + 256 * r;
            int kk = idx >> 4, q4 = (idx & 15) * 4;
            vw[r] = *reinterpret_cast<const float4*>(W + kk * Cn + d0 + q4);
        }
#pragma unroll
        for (int r = 0; r < 12; r++) {
            int idx = tid + 256 * r;
            int kk = idx >> 4, q4 = (idx & 15) * 4;
            w_s[(q4 + 0) * GSTR + kk] = vw[r].x;
            w_s[(q4 + 1) * GSTR + kk] = vw[r].y;
            w_s[(q4 + 2) * GSTR + kk] = vw[r].z;
            w_s[(q4 + 3) * GSTR + kk] = vw[r].w;
        }
    }
    __syncthreads();

    u64t acc2[4][4] = {};
#pragma unroll 8
    for (int kk = 0; kk < Cn; kk += 2) {
        u64t a2[4], w2[4];
#pragma unroll
        for (int i = 0; i < 4; i++) a2[i] = lds2(&a_s[(ty + 16 * i) * GSTR + kk]);
#pragma unroll
        for (int j = 0; j < 4; j++) w2[j] = lds2(&w_s[(tx + 16 * j) * GSTR + kk]);
#pragma unroll
        for (int i = 0; i < 4; i++)
#pragma unroll
            for (int j = 0; j < 4; j++) acc2[i][j] = fma2(a2[i], w2[j], acc2[i][j]);
    }
    float* ob = out + b * Tn * Cn;
#pragma unroll
    for (int i = 0; i < 4; i++) {
        int t = t0 + ty + 16 * i;
#pragma unroll
        for (int j = 0; j < 4; j++) {
            int d = d0 + tx + 16 * j;
            ob[t * Cn + d] = lohi_sum(acc2[i][j]) + bias[d];
        }
    }
}

// ---------------------------------------------------------------------------
// Single-pass banded attention: cp.async K/V pipeline, mask prefetch in the
// async shadow, d-paired PV (row-major V, no transpose).
// ---------------------------------------------------------------------------
__global__ void __launch_bounds__(256, 2)
attn_kernel(const float* __restrict__ embk, const float* __restrict__ embv,
            const int* __restrict__ mask) {
    extern __shared__ float sm[];
    float* qs   = sm;                     // [64][100]
    float* Ks   = qs + TQ * KVS;          // [64][100]
    float* Vs   = Ks + TQ * KVS;          // [64][100]  row-major
    float* P    = Vs + TQ * KVS;          // [64][80]
    float* rq   = P + TQ * PSTR;          // [64][12]
    float* pTap = rq + TQ * 12;           // [64][12]
    float* lr   = pTap + TQ * 12;         // [64]
    float* prox = lr + TQ;                // [260]

    const int tx = threadIdx.x, ty = threadIdx.y;
    const int tid = ty * 16 + tx;
    const int b = blockIdx.y / Hn, h = blockIdx.y % Hn;
    const int t0 = blockIdx.x * TQ;
    const int sbase = t0 - BAND;

    const float* Qb = g_q + (b * Tn) * Cn + h * Kd;
    const float* Kb = g_k + (b * Tn) * Cn + h * Kd;
    const float* Vb = g_v + (b * Tn) * Cn + h * Kd;

    // issue chunk 0 loads immediately
#pragma unroll
    for (int r = 0; r < 6; r++) {
        int idx = tid + 256 * r;
        int row = idx / 24, c4 = (idx % 24) * 4;
        int s = sbase + row;
        int sc = s < 0 ? 0 : (s >= Tn ? Tn - 1 : s);
        cpa16(&Ks[row * KVS + c4], Kb + sc * Cn + c4);
        cpa16(&Vs[row * KVS + c4], Vb + sc * Cn + c4);
    }
    cpa_commit();

    for (int i = tid; i < TQ * 12; i += 256) pTap[i] = 0.f;
    for (int i = tid; i <= BAND; i += 256) prox[i] = log1pf((float)i);

    const float qsc = 0.10206207261596575f;
#pragma unroll
    for (int r = 0; r < 6; r++) {
        int idx = tid + 256 * r;
        int row = idx / 24, c4 = (idx % 24) * 4;
        float4 v = *reinterpret_cast<const float4*>(Qb + (t0 + row) * Cn + c4);
        float* d = qs + row * KVS + c4;
        d[0] = v.x * qsc; d[1] = v.y * qsc; d[2] = v.z * qsc; d[3] = v.w * qsc;
    }
    __syncthreads();   // qs visible for rq

    // rel-K per-query logits
    for (int idx = tid; idx < TQ * 9; idx += 256) {
        int q = idx / 9, m = idx - q * 9;
        const float* e  = embk + m * Kd;
        const float* qp = qs + q * KVS;
        float s = 0.f;
#pragma unroll 8
        for (int kk = 0; kk < Kd; kk++) s += qp[kk] * e[kk];
        rq[q * 12 + m] = s;
    }

    float o[4][6] = {};
    float lsum[4] = {};

    for (int ch = 0; ch < NCH; ch++) {
        // mask prefetch (overlaps cp.async), packed into 16 predicate bits
        unsigned mbits = 0;
        {
            const int* mb = mask + b * Tn * Tn;
#pragma unroll
            for (int i = 0; i < 4; i++) {
                int t = t0 + ty + 16 * i;
#pragma unroll
                for (int j = 0; j < 4; j++) {
                    int s = sbase + ch * 64 + tx + 16 * j;
                    int d = s - t;
                    int ad = d < 0 ? -d : d;
                    bool valid = (s >= 0) && (s < Tn) && (ad <= BAND);
                    if (valid) valid = (mb[t * Tn + s] != 0);
                    if (valid) mbits |= 1u << (i * 4 + j);
                }
            }
        }
        cpa_wait0();
        __syncthreads();   // Ks/Vs(ch) ready; rq ready (first iter)

        // QK^T, kk paired into f32x2
        u64t acc2[4][4] = {};
#pragma unroll 4
        for (int kk = 0; kk < Kd; kk += 2) {
            u64t q2[4], k2[4];
#pragma unroll
            for (int i = 0; i < 4; i++) q2[i] = lds2(&qs[(ty + 16 * i) * KVS + kk]);
#pragma unroll
            for (int j = 0; j < 4; j++) k2[j] = lds2(&Ks[(tx + 16 * j) * KVS + kk]);
#pragma unroll
            for (int i = 0; i < 4; i++)
#pragma unroll
                for (int j = 0; j < 4; j++) acc2[i][j] = fma2(q2[i], k2[j], acc2[i][j]);
        }

        // epilogue: rel-k tap + proximal bias + mask + exp
#pragma unroll
        for (int i = 0; i < 4; i++) {
            int q = ty + 16 * i, t = t0 + q;
#pragma unroll
            for (int j = 0; j < 4; j++) {
                int sl = tx + 16 * j;
                int s = sbase + ch * 64 + sl;
                int d = s - t;
                int ad = d < 0 ? -d : d;
                float v = lohi_sum(acc2[i][j]);
                if (ad <= WIN) v += rq[q * 12 + d + WIN];
                v -= prox[ad <= BAND ? ad : BAND];
                float e = (mbits >> (i * 4 + j)) & 1u ? __expf(v) : 0.f;
                P[q * PSTR + sl] = e;
                if (ad <= WIN) pTap[q * 12 + d + WIN] = e;
                lsum[i] += e;
            }
        }
        __syncthreads();   // P visible; QK done with Ks

        // O += P @ V, d-paired (row-major V, contiguous d)
        {
            u64t o2[4][3] = {};
#pragma unroll 2
            for (int sl = 0; sl < 64; sl++) {
                u64t pd[4], v2[3];
#pragma unroll
                for (int i = 0; i < 4; i++) pd[i] = dup2(P[(ty + 16 * i) * PSTR + sl]);
#pragma unroll
                for (int jj = 0; jj < 3; jj++) v2[jj] = lds2(&Vs[sl * KVS + 2 * tx + 32 * jj]);
#pragma unroll
                for (int i = 0; i < 4; i++)
#pragma unroll
                    for (int jj = 0; jj < 3; jj++) o2[i][jj] = fma2(pd[i], v2[jj], o2[i][jj]);
            }
#pragma unroll
            for (int i = 0; i < 4; i++)
#pragma unroll
                for (int jj = 0; jj < 3; jj++) {
                    float2 f = unpk(o2[i][jj]);
                    o[i][2 * jj] += f.x;
                    o[i][2 * jj + 1] += f.y;
                }
        }
        __syncthreads();   // PV done with Vs/P

        // issue next chunk loads
        if (ch + 1 < NCH) {
#pragma unroll
            for (int r = 0; r < 6; r++) {
                int idx = tid + 256 * r;
                int row = idx / 24, c4 = (idx % 24) * 4;
                int s = sbase + (ch + 1) * 64 + row;
                int sc = s < 0 ? 0 : (s >= Tn ? Tn - 1 : s);
                cpa16(&Ks[row * KVS + c4], Kb + sc * Cn + c4);
                cpa16(&Vs[row * KVS + c4], Vb + sc * Cn + c4);
            }
            cpa_commit();
        }
    }

    // reduce row sums across the 16 tx lanes
#pragma unroll
    for (int i = 0; i < 4; i++) {
        float l = lsum[i];
        l += __shfl_xor_sync(0xffffffffu, l, 1);
        l += __shfl_xor_sync(0xffffffffu, l, 2);
        l += __shfl_xor_sync(0xffffffffu, l, 4);
        l += __shfl_xor_sync(0xffffffffu, l, 8);
        if (tx == 0) lr[ty + 16 * i] = l;
    }
    __syncthreads();

    // rel-V taps + normalize + store (d-pairs at 2tx+32jj)
#pragma unroll
    for (int i = 0; i < 4; i++) {
        int q = ty + 16 * i;
        float inv = 1.0f / lr[q];
#pragma unroll
        for (int m = 0; m < 9; m++) {
            float p = pTap[q * 12 + m];
#pragma unroll
            for (int jj = 0; jj < 3; jj++) {
                float2 e2 = *reinterpret_cast<const float2*>(embv + m * Kd + 2 * tx + 32 * jj);
                o[i][2 * jj]     += p * e2.x;
                o[i][2 * jj + 1] += p * e2.y;
            }
        }
        float* ob = g_att + (b * Tn + t0 + q) * Cn + h * Kd;
#pragma unroll
        for (int jj = 0; jj < 3; jj++) {
            float2 w;
            w.x = o[i][2 * jj] * inv;
            w.y = o[i][2 * jj + 1] * inv;
            *reinterpret_cast<float2*>(ob + 2 * tx + 32 * jj) = w;
        }
    }
}

// ---------------------------------------------------------------------------
// Output projection + transpose, single-fill (A via cp.async — redundancy-free
// since att rows are contiguous; W transposed manually).
// ---------------------------------------------------------------------------
__global__ void __launch_bounds__(256)
outproj_kernel(const float* __restrict__ Wo, const float* __restrict__ bo,
               float* __restrict__ out) {
    extern __shared__ float smp[];
    float* a_s = smp;               // [64][196]  (t, dd)
    float* w_s = smp + 64 * GSTR;   // [64][196]  (co, dd)
    const int b = blockIdx.z;
    const int t0 = blockIdx.x * 64, c0 = blockIdx.y * 64;
    const int tx = threadIdx.x, ty = threadIdx.y, tid = ty * 16 + tx;
    const float* ab = g_att + b * Tn * Cn;

    // A tile straight copy (row t contiguous over dd)
#pragma unroll
    for (int r = 0; r < 12; r++) {
        int idx = tid + 256 * r;
        int t = idx / 48, dq = (idx % 48) * 4;
        cpa16(&a_s[t * GSTR + dq], ab + (t0 + t) * Cn + dq);
    }
    cpa_commit();
    // W transpose [dd][co] -> [co][dd]
    {
        float4 vw[12];
#pragma unroll
        for (int r = 0; r < 12; r++) {
            int idx = tid + 256 * r;
            int kk = idx >> 4, q4 = (idx & 15) * 4;
            vw[r] = *reinterpret_cast<const float4*>(Wo + kk * Cn + c0 + q4);
        }
#pragma unroll
        for (int r = 0; r < 12; r++) {
            int idx = tid + 256 * r;
            int kk = idx >> 4, q4 = (idx & 15) * 4;
            w_s[(q4 + 0) * GSTR + kk] = vw[r].x;
            w_s[(q4 + 1) * GSTR + kk] = vw[r].y;
            w_s[(q4 + 2) * GSTR + kk] = vw[r].z;
            w_s[(q4 + 3) * GSTR + kk] = vw[r].w;
        }
    }
    cpa_wait0();
    __syncthreads();

    u64t acc2[4][4] = {};
#pragma unroll 8
    for (int kk = 0; kk < Cn; kk += 2) {
        u64t w2[4], a2[4];
#pragma unroll
        for (int i = 0; i < 4; i++) w2[i] = lds2(&w_s[(ty + 16 * i) * GSTR + kk]);
#pragma unroll
        for (int j = 0; j < 4; j++) a2[j] = lds2(&a_s[(tx + 16 * j) * GSTR + kk]);
#pragma unroll
        for (int i = 0; i < 4; i++)
#pragma unroll
            for (int j = 0; j < 4; j++) acc2[i][j] = fma2(w2[i], a2[j], acc2[i][j]);
    }
#pragma unroll
    for (int i = 0; i < 4; i++) {
        int co = c0 + ty + 16 * i;
        float bb = bo[co];
#pragma unroll
        for (int j = 0; j < 4; j++)
            out[(b * Cn + co) * Tn + t0 + tx + 16 * j] = lohi_sum(acc2[i][j]) + bb;
    }
}

// ---------------------------------------------------------------------------
extern "C" void kernel_launch(void* const* d_in, const int* in_sizes, int n_in,
                              void* d_out, int out_size) {
    (void)in_sizes; (void)n_in; (void)out_size;
    const float* x   = (const float*)d_in[0];
    const float* c   = (const float*)d_in[1];
    const float* Wq  = (const float*)d_in[2];
    const float* bq  = (const float*)d_in[3];
    const float* Wk  = (const float*)d_in[4];
    const float* bk  = (const float*)d_in[5];
    const float* Wv  = (const float*)d_in[6];
    const float* bv  = (const float*)d_in[7];
    const float* Wo  = (const float*)d_in[8];
    const float* bo  = (const float*)d_in[9];
    const float* ek  = (const float*)d_in[10];
    const float* ev  = (const float*)d_in[11];
    const int*   msk = (const int*)d_in[12];

    const int attn_smem = ATTN_SMEM_FLOATS * (int)sizeof(float);
    cudaFuncSetAttribute(attn_kernel, cudaFuncAttributeMaxDynamicSharedMemorySize, attn_smem);
    cudaFuncSetAttribute(proj_kernel, cudaFuncAttributeMaxDynamicSharedMemorySize, GEMM_SMEM_BYTES);
    cudaFuncSetAttribute(outproj_kernel, cudaFuncAttributeMaxDynamicSharedMemorySize, GEMM_SMEM_BYTES);

    proj_kernel<<<dim3(Tn / 64, Cn / 64, Bn * 3), dim3(16, 16), GEMM_SMEM_BYTES>>>(
        x, c, Wq, bq, Wk, bk, Wv, bv);
    attn_kernel<<<dim3(Tn / TQ, Bn * Hn), dim3(16, 16), attn_smem>>>(ek, ev, msk);
    outproj_kernel<<<dim3(Tn / 64, Cn / 64, Bn), dim3(16, 16), GEMM_SMEM_BYTES>>>(
        Wo, bo, (float*)d_out);
}

// round 7
// speedup vs baseline: 1.4835x; 1.0731x over previous
#include <cuda_runtime.h>
#include <math.h>

namespace {
constexpr int Bn = 4, Cn = 192, Tn = 2048, Hn = 2, Kd = 96;
constexpr int TQ = 64;
constexpr int BAND = 256;
constexpr int WIN = 4;
constexpr int SPAN = TQ + 2 * BAND;   // 576
constexpr int NCH = SPAN / 64;        // 9
constexpr int KVS  = 100;             // q/K/V stride: mult of 4 (cp.async), even (LDS.64)
constexpr int PSTR = 80;
constexpr int GSTR = 194;             // proj staging stride: ==2 mod 32 -> conflict-free
constexpr int ATTN_SMEM_FLOATS = 3 * TQ * KVS + TQ * PSTR + TQ * 12 + TQ * 12 + TQ + 260
                               + (NCH * 256 * 2 + 3) / 4;  // + ushort mbs[9][256]
constexpr int GEMM_SMEM_BYTES  = 2 * 64 * GSTR * 4;        // 99.3KB
constexpr int OASTR = 196;            // outproj A stride (cp.async 16B alignment)
constexpr int OWSTR = 194;            // outproj W stride (conflict-free scalar stores)
constexpr int OUT_SMEM_BYTES = 64 * (OASTR + OWSTR) * 4;   // 99.8KB
}

__device__ __align__(16) float g_q[Bn * Tn * Cn];
__device__ __align__(16) float g_k[Bn * Tn * Cn];
__device__ __align__(16) float g_v[Bn * Tn * Cn];
__device__ __align__(16) float g_att[Bn * Tn * Cn];

typedef unsigned long long u64t;

__device__ __forceinline__ u64t fma2(u64t a, u64t b, u64t c) {
    u64t d;
    asm("fma.rn.f32x2 %0, %1, %2, %3;" : "=l"(d) : "l"(a), "l"(b), "l"(c));
    return d;
}
__device__ __forceinline__ float lohi_sum(u64t v) {
    float2 f = *reinterpret_cast<float2*>(&v);
    return f.x + f.y;
}
__device__ __forceinline__ float2 unpk(u64t v) { return *reinterpret_cast<float2*>(&v); }
__device__ __forceinline__ u64t lds2(const float* p) {
    return *reinterpret_cast<const u64t*>(p);
}
__device__ __forceinline__ u64t dup2(float p) {
    u64t r;
    asm("mov.b64 %0, {%1, %1};" : "=l"(r) : "f"(p));
    return r;
}
__device__ __forceinline__ void cpa16(float* s, const float* g) {
    asm volatile("cp.async.cg.shared.global [%0], [%1], 16;"
                 :: "r"((unsigned)__cvta_generic_to_shared(s)), "l"(g));
}
__device__ __forceinline__ void cpa_commit() { asm volatile("cp.async.commit_group;"); }
__device__ __forceinline__ void cpa_wait0()  { asm volatile("cp.async.wait_group 0;"); }

// ---------------------------------------------------------------------------
// Q/K/V projections, single-fill with conflict-free transposed staging.
// Fill: lane=(a,kl): t4=4a+16*phase, kk=kl+8w+64r -> store bank = 8a+kl (all 32).
// ---------------------------------------------------------------------------
__global__ void __launch_bounds__(256)
proj_kernel(const float* __restrict__ xin, const float* __restrict__ cin,
            const float* __restrict__ Wq, const float* __restrict__ bq,
            const float* __restrict__ Wk, const float* __restrict__ bk,
            const float* __restrict__ Wv, const float* __restrict__ bv) {
    extern __shared__ float smp[];
    float* a_s = smp;               // [64 t][GSTR kk]
    float* w_s = smp + 64 * GSTR;   // [64 d][GSTR kk]
    const int which = blockIdx.z % 3;
    const int b = blockIdx.z / 3;
    const float* in   = (which == 0) ? xin : cin;
    const float* W    = (which == 0) ? Wq : (which == 1) ? Wk : Wv;
    const float* bias = (which == 0) ? bq : (which == 1) ? bk : bv;
    float* out        = (which == 0) ? g_q : (which == 1) ? g_k : g_v;
    const int t0 = blockIdx.x * 64, d0 = blockIdx.y * 64;
    const int tx = threadIdx.x, ty = threadIdx.y, tid = ty * 16 + tx;
    const int lane = tid & 31, wrp = tid >> 5;
    const int la = lane & 3, kl = lane >> 2;
    const float* inb = in + b * Cn * Tn;

    // fill A ([kk][t] -> [t][kk]), batched loads then conflict-free stores
    {
        float4 va[12];
#pragma unroll
        for (int r = 0; r < 3; r++)
#pragma unroll
            for (int ph = 0; ph < 4; ph++) {
                int kk = kl + 8 * wrp + 64 * r;
                int t4 = 4 * la + 16 * ph;
                va[r * 4 + ph] = *reinterpret_cast<const float4*>(inb + kk * Tn + t0 + t4);
            }
#pragma unroll
        for (int r = 0; r < 3; r++)
#pragma unroll
            for (int ph = 0; ph < 4; ph++) {
                int kk = kl + 8 * wrp + 64 * r;
                int t4 = 4 * la + 16 * ph;
                float4 v = va[r * 4 + ph];
                a_s[(t4 + 0) * GSTR + kk] = v.x;
                a_s[(t4 + 1) * GSTR + kk] = v.y;
                a_s[(t4 + 2) * GSTR + kk] = v.z;
                a_s[(t4 + 3) * GSTR + kk] = v.w;
            }
    }
    // fill W ([kk][d] -> [d][kk])
    {
        float4 vw[12];
#pragma unroll
        for (int r = 0; r < 3; r++)
#pragma unroll
            for (int ph = 0; ph < 4; ph++) {
                int kk = kl + 8 * wrp + 64 * r;
                int d4 = 4 * la + 16 * ph;
                vw[r * 4 + ph] = *reinterpret_cast<const float4*>(W + kk * Cn + d0 + d4);
            }
#pragma unroll
        for (int r = 0; r < 3; r++)
#pragma unroll
            for (int ph = 0; ph < 4; ph++) {
                int kk = kl + 8 * wrp + 64 * r;
                int d4 = 4 * la + 16 * ph;
                float4 v = vw[r * 4 + ph];
                w_s[(d4 + 0) * GSTR + kk] = v.x;
                w_s[(d4 + 1) * GSTR + kk] = v.y;
                w_s[(d4 + 2) * GSTR + kk] = v.z;
                w_s[(d4 + 3) * GSTR + kk] = v.w;
            }
    }
    __syncthreads();

    u64t acc2[4][4] = {};
#pragma unroll 8
    for (int kk = 0; kk < Cn; kk += 2) {
        u64t a2[4], w2[4];
#pragma unroll
        for (int i = 0; i < 4; i++) a2[i] = lds2(&a_s[(ty + 16 * i) * GSTR + kk]);
#pragma unroll
        for (int j = 0; j < 4; j++) w2[j] = lds2(&w_s[(tx + 16 * j) * GSTR + kk]);
#pragma unroll
        for (int i = 0; i < 4; i++)
#pragma unroll
            for (int j = 0; j < 4; j++) acc2[i][j] = fma2(a2[i], w2[j], acc2[i][j]);
    }
    float* ob = out + b * Tn * Cn;
#pragma unroll
    for (int i = 0; i < 4; i++) {
        int t = t0 + ty + 16 * i;
#pragma unroll
        for (int j = 0; j < 4; j++) {
            int d = d0 + tx + 16 * j;
            ob[t * Cn + d] = lohi_sum(acc2[i][j]) + bias[d];
        }
    }
}

// ---------------------------------------------------------------------------
// Single-pass banded attention: cp.async K/V pipeline; ALL mask loads hoisted
// to the prologue (packed 16 bits/chunk into per-thread smem stash).
// ---------------------------------------------------------------------------
__global__ void __launch_bounds__(256, 2)
attn_kernel(const float* __restrict__ embk, const float* __restrict__ embv,
            const int* __restrict__ mask) {
    extern __shared__ float sm[];
    float* qs   = sm;                     // [64][100]
    float* Ks   = qs + TQ * KVS;          // [64][100]
    float* Vs   = Ks + TQ * KVS;          // [64][100]  row-major
    float* P    = Vs + TQ * KVS;          // [64][80]
    float* rq   = P + TQ * PSTR;          // [64][12]
    float* pTap = rq + TQ * 12;           // [64][12]
    float* lr   = pTap + TQ * 12;         // [64]
    float* prox = lr + TQ;                // [260]
    unsigned short* mbs = reinterpret_cast<unsigned short*>(prox + 260); // [9][256]

    const int tx = threadIdx.x, ty = threadIdx.y;
    const int tid = ty * 16 + tx;
    const int b = blockIdx.y / Hn, h = blockIdx.y % Hn;
    const int t0 = blockIdx.x * TQ;
    const int sbase = t0 - BAND;

    const float* Qb = g_q + (b * Tn) * Cn + h * Kd;
    const float* Kb = g_k + (b * Tn) * Cn + h * Kd;
    const float* Vb = g_v + (b * Tn) * Cn + h * Kd;

    // issue chunk 0 K/V loads immediately
#pragma unroll
    for (int r = 0; r < 6; r++) {
        int idx = tid + 256 * r;
        int row = idx / 24, c4 = (idx % 24) * 4;
        int s = sbase + row;
        int sc = s < 0 ? 0 : (s >= Tn ? Tn - 1 : s);
        cpa16(&Ks[row * KVS + c4], Kb + sc * Cn + c4);
        cpa16(&Vs[row * KVS + c4], Vb + sc * Cn + c4);
    }
    cpa_commit();

    for (int i = tid; i < TQ * 12; i += 256) pTap[i] = 0.f;
    for (int i = tid; i <= BAND; i += 256) prox[i] = log1pf((float)i);

    // load Q (pre-scaled)
    const float qsc = 0.10206207261596575f;
#pragma unroll
    for (int r = 0; r < 6; r++) {
        int idx = tid + 256 * r;
        int row = idx / 24, c4 = (idx % 24) * 4;
        float4 v = *reinterpret_cast<const float4*>(Qb + (t0 + row) * Cn + c4);
        float* d = qs + row * KVS + c4;
        d[0] = v.x * qsc; d[1] = v.y * qsc; d[2] = v.z * qsc; d[3] = v.w * qsc;
    }

    // hoist ALL mask loads: 16 bits per chunk, stashed thread-private in smem
    {
        const int* mb = mask + b * Tn * Tn;
#pragma unroll
        for (int ch = 0; ch < NCH; ch++) {
            unsigned bits = 0;
#pragma unroll
            for (int i = 0; i < 4; i++) {
                int t = t0 + ty + 16 * i;
#pragma unroll
                for (int j = 0; j < 4; j++) {
                    int s = sbase + ch * 64 + tx + 16 * j;
                    int d = s - t;
                    int ad = d < 0 ? -d : d;
                    bool valid = (s >= 0) && (s < Tn) && (ad <= BAND);
                    if (valid) valid = (mb[t * Tn + s] != 0);
                    if (valid) bits |= 1u << (i * 4 + j);
                }
            }
            mbs[ch * 256 + tid] = (unsigned short)bits;
        }
    }
    __syncthreads();   // qs visible for rq

    // rel-K per-query logits
    for (int idx = tid; idx < TQ * 9; idx += 256) {
        int q = idx / 9, m = idx - q * 9;
        const float* e  = embk + m * Kd;
        const float* qp = qs + q * KVS;
        float s = 0.f;
#pragma unroll 8
        for (int kk = 0; kk < Kd; kk++) s += qp[kk] * e[kk];
        rq[q * 12 + m] = s;
    }

    float o[4][6] = {};
    float lsum[4] = {};

    for (int ch = 0; ch < NCH; ch++) {
        cpa_wait0();
        __syncthreads();   // Ks/Vs(ch) ready; rq ready (first iter)

        // QK^T, kk paired into f32x2
        u64t acc2[4][4] = {};
#pragma unroll 4
        for (int kk = 0; kk < Kd; kk += 2) {
            u64t q2[4], k2[4];
#pragma unroll
            for (int i = 0; i < 4; i++) q2[i] = lds2(&qs[(ty + 16 * i) * KVS + kk]);
#pragma unroll
            for (int j = 0; j < 4; j++) k2[j] = lds2(&Ks[(tx + 16 * j) * KVS + kk]);
#pragma unroll
            for (int i = 0; i < 4; i++)
#pragma unroll
                for (int j = 0; j < 4; j++) acc2[i][j] = fma2(q2[i], k2[j], acc2[i][j]);
        }

        // epilogue: rel-k tap + proximal bias + mask bits + exp
        unsigned mbits = mbs[ch * 256 + tid];
#pragma unroll
        for (int i = 0; i < 4; i++) {
            int q = ty + 16 * i, t = t0 + q;
#pragma unroll
            for (int j = 0; j < 4; j++) {
                int sl = tx + 16 * j;
                int s = sbase + ch * 64 + sl;
                int d = s - t;
                int ad = d < 0 ? -d : d;
                float v = lohi_sum(acc2[i][j]);
                if (ad <= WIN) v += rq[q * 12 + d + WIN];
                v -= prox[ad <= BAND ? ad : BAND];
                float e = (mbits >> (i * 4 + j)) & 1u ? __expf(v) : 0.f;
                P[q * PSTR + sl] = e;
                if (ad <= WIN) pTap[q * 12 + d + WIN] = e;
                lsum[i] += e;
            }
        }
        __syncthreads();   // P visible; QK done with Ks

        // O += P @ V, d-paired (row-major V)
        {
            u64t o2[4][3] = {};
#pragma unroll 2
            for (int sl = 0; sl < 64; sl++) {
                u64t pd[4], v2[3];
#pragma unroll
                for (int i = 0; i < 4; i++) pd[i] = dup2(P[(ty + 16 * i) * PSTR + sl]);
#pragma unroll
                for (int jj = 0; jj < 3; jj++) v2[jj] = lds2(&Vs[sl * KVS + 2 * tx + 32 * jj]);
#pragma unroll
                for (int i = 0; i < 4; i++)
#pragma unroll
                    for (int jj = 0; jj < 3; jj++) o2[i][jj] = fma2(pd[i], v2[jj], o2[i][jj]);
            }
#pragma unroll
            for (int i = 0; i < 4; i++)
#pragma unroll
                for (int jj = 0; jj < 3; jj++) {
                    float2 f = unpk(o2[i][jj]);
                    o[i][2 * jj] += f.x;
                    o[i][2 * jj + 1] += f.y;
                }
        }
        __syncthreads();   // PV done with Vs/P

        // issue next chunk loads
        if (ch + 1 < NCH) {
#pragma unroll
            for (int r = 0; r < 6; r++) {
                int idx = tid + 256 * r;
                int row = idx / 24, c4 = (idx % 24) * 4;
                int s = sbase + (ch + 1) * 64 + row;
                int sc = s < 0 ? 0 : (s >= Tn ? Tn - 1 : s);
                cpa16(&Ks[row * KVS + c4], Kb + sc * Cn + c4);
                cpa16(&Vs[row * KVS + c4], Vb + sc * Cn + c4);
            }
            cpa_commit();
        }
    }

    // reduce row sums across the 16 tx lanes
#pragma unroll
    for (int i = 0; i < 4; i++) {
        float l = lsum[i];
        l += __shfl_xor_sync(0xffffffffu, l, 1);
        l += __shfl_xor_sync(0xffffffffu, l, 2);
        l += __shfl_xor_sync(0xffffffffu, l, 4);
        l += __shfl_xor_sync(0xffffffffu, l, 8);
        if (tx == 0) lr[ty + 16 * i] = l;
    }
    __syncthreads();

    // rel-V taps + normalize + store
#pragma unroll
    for (int i = 0; i < 4; i++) {
        int q = ty + 16 * i;
        float inv = 1.0f / lr[q];
#pragma unroll
        for (int m = 0; m < 9; m++) {
            float p = pTap[q * 12 + m];
#pragma unroll
            for (int jj = 0; jj < 3; jj++) {
                float2 e2 = *reinterpret_cast<const float2*>(embv + m * Kd + 2 * tx + 32 * jj);
                o[i][2 * jj]     += p * e2.x;
                o[i][2 * jj + 1] += p * e2.y;
            }
        }
        float* ob = g_att + (b * Tn + t0 + q) * Cn + h * Kd;
#pragma unroll
        for (int jj = 0; jj < 3; jj++) {
            float2 w;
            w.x = o[i][2 * jj] * inv;
            w.y = o[i][2 * jj + 1] * inv;
            *reinterpret_cast<float2*>(ob + 2 * tx + 32 * jj) = w;
        }
    }
}

// ---------------------------------------------------------------------------
// Output projection + transpose, single-fill; W staged with the conflict-free
// mapping, A streamed in via cp.async (contiguous rows).
// ---------------------------------------------------------------------------
__global__ void __launch_bounds__(256)
outproj_kernel(const float* __restrict__ Wo, const float* __restrict__ bo,
               float* __restrict__ out) {
    extern __shared__ float smp[];
    float* a_s = smp;                // [64 t][OASTR dd]
    float* w_s = smp + 64 * OASTR;   // [64 co][OWSTR dd]
    const int b = blockIdx.z;
    const int t0 = blockIdx.x * 64, c0 = blockIdx.y * 64;
    const int tx = threadIdx.x, ty = threadIdx.y, tid = ty * 16 + tx;
    const int lane = tid & 31, wrp = tid >> 5;
    const int la = lane & 3, kl = lane >> 2;
    const float* ab = g_att + b * Tn * Cn;

    // A tile straight copy (rows contiguous over dd)
#pragma unroll
    for (int r = 0; r < 12; r++) {
        int idx = tid + 256 * r;
        int t = idx / 48, dq = (idx % 48) * 4;
        cpa16(&a_s[t * OASTR + dq], ab + (t0 + t) * Cn + dq);
    }
    cpa_commit();
    // W transpose [dd][co] -> [co][dd], conflict-free mapping
    {
        float4 vw[12];
#pragma unroll
        for (int r = 0; r < 3; r++)
#pragma unroll
            for (int ph = 0; ph < 4; ph++) {
                int kk = kl + 8 * wrp + 64 * r;
                int d4 = 4 * la + 16 * ph;
                vw[r * 4 + ph] = *reinterpret_cast<const float4*>(Wo + kk * Cn + c0 + d4);
            }
#pragma unroll
        for (int r = 0; r < 3; r++)
#pragma unroll
            for (int ph = 0; ph < 4; ph++) {
                int kk = kl + 8 * wrp + 64 * r;
                int d4 = 4 * la + 16 * ph;
                float4 v = vw[r * 4 + ph];
                w_s[(d4 + 0) * OWSTR + kk] = v.x;
                w_s[(d4 + 1) * OWSTR + kk] = v.y;
                w_s[(d4 + 2) * OWSTR + kk] = v.z;
                w_s[(d4 + 3) * OWSTR + kk] = v.w;
            }
    }
    cpa_wait0();
    __syncthreads();

    u64t acc2[4][4] = {};
#pragma unroll 8
    for (int kk = 0; kk < Cn; kk += 2) {
        u64t w2[4], a2[4];
#pragma unroll
        for (int i = 0; i < 4; i++) w2[i] = lds2(&w_s[(ty + 16 * i) * OWSTR + kk]);
#pragma unroll
        for (int j = 0; j < 4; j++) a2[j] = lds2(&a_s[(tx + 16 * j) * OASTR + kk]);
#pragma unroll
        for (int i = 0; i < 4; i++)
#pragma unroll
            for (int j = 0; j < 4; j++) acc2[i][j] = fma2(w2[i], a2[j], acc2[i][j]);
    }
#pragma unroll
    for (int i = 0; i < 4; i++) {
        int co = c0 + ty + 16 * i;
        float bb = bo[co];
#pragma unroll
        for (int j = 0; j < 4; j++)
            out[(b * Cn + co) * Tn + t0 + tx + 16 * j] = lohi_sum(acc2[i][j]) + bb;
    }
}

// ---------------------------------------------------------------------------
extern "C" void kernel_launch(void* const* d_in, const int* in_sizes, int n_in,
                              void* d_out, int out_size) {
    (void)in_sizes; (void)n_in; (void)out_size;
    const float* x   = (const float*)d_in[0];
    const float* c   = (const float*)d_in[1];
    const float* Wq  = (const float*)d_in[2];
    const float* bq  = (const float*)d_in[3];
    const float* Wk  = (const float*)d_in[4];
    const float* bk  = (const float*)d_in[5];
    const float* Wv  = (const float*)d_in[6];
    const float* bv  = (const float*)d_in[7];
    const float* Wo  = (const float*)d_in[8];
    const float* bo  = (const float*)d_in[9];
    const float* ek  = (const float*)d_in[10];
    const float* ev  = (const float*)d_in[11];
    const int*   msk = (const int*)d_in[12];

    const int attn_smem = ATTN_SMEM_FLOATS * (int)sizeof(float);
    cudaFuncSetAttribute(attn_kernel, cudaFuncAttributeMaxDynamicSharedMemorySize, attn_smem);
    cudaFuncSetAttribute(proj_kernel, cudaFuncAttributeMaxDynamicSharedMemorySize, GEMM_SMEM_BYTES);
    cudaFuncSetAttribute(outproj_kernel, cudaFuncAttributeMaxDynamicSharedMemorySize, OUT_SMEM_BYTES);

    proj_kernel<<<dim3(Tn / 64, Cn / 64, Bn * 3), dim3(16, 16), GEMM_SMEM_BYTES>>>(
        x, c, Wq, bq, Wk, bk, Wv, bv);
    attn_kernel<<<dim3(Tn / TQ, Bn * Hn), dim3(16, 16), attn_smem>>>(ek, ev, msk);
    outproj_kernel<<<dim3(Tn / 64, Cn / 64, Bn), dim3(16, 16), OUT_SMEM_BYTES>>>(
        Wo, bo, (float*)d_out);
}